// round 2
// baseline (speedup 1.0000x reference)
#include <cuda_runtime.h>
#include <cuda_bf16.h>

// Problem constants (fixed by the dataset)
#define NN      64
#define C_TOT   64
#define W_IN    4096
#define FF      64
#define KW      9
#define OUT_W   (W_IN - KW + 1)   // 4088

// Tiling
#define TW      128               // output positions per block
#define CCHUNK  8                 // channels per smem stage
#define THREADS 256
#define N_TILES ((OUT_W + TW - 1) / TW)   // 32

__global__ __launch_bounds__(THREADS)
void conv1d_direct_kernel(const float* __restrict__ x,
                          const float* __restrict__ filt,
                          const float* __restrict__ bias,
                          float* __restrict__ out)
{
    // x tile: CCHUNK rows of (TW + 8) = 136 inputs (need 135, +1 pad)
    __shared__ float sx[CCHUNK][TW + 8];      // 4.25 KB
    // filt tile transposed to [c][w][f] so 8 consecutive f are contiguous (float4)
    __shared__ float sf[CCHUNK][KW][FF];      // 18 KB

    const int tile = blockIdx.x;          // 0..31
    const int n    = blockIdx.y;          // 0..63
    const int t0   = tile * TW;
    const int tid  = threadIdx.x;
    const int lane = tid & 31;
    const int warp = tid >> 5;            // 0..7
    const int fbase = warp * 8;           // this warp's 8 filters
    const int tloc  = lane * 4;           // this lane's 4 outputs within tile

    float acc[8][4];
    #pragma unroll
    for (int i = 0; i < 8; ++i)
        #pragma unroll
        for (int j = 0; j < 4; ++j)
            acc[i][j] = 0.0f;

    for (int c0 = 0; c0 < C_TOT; c0 += CCHUNK) {
        __syncthreads();

        // ---- stage x tile: [CCHUNK][136], clamp reads past W_IN to 0 ----
        #pragma unroll 1
        for (int idx = tid; idx < CCHUNK * (TW + 8); idx += THREADS) {
            int c = idx / (TW + 8);
            int t = idx - c * (TW + 8);
            int tg = t0 + t;
            float v = 0.0f;
            if (tg < W_IN)
                v = x[((size_t)n * C_TOT + c0 + c) * W_IN + tg];
            sx[c][t] = v;
        }

        // ---- stage filt tile transposed: sf[c][w][f] = filt[f][c0+c][w] ----
        #pragma unroll 1
        for (int idx = tid; idx < CCHUNK * KW * FF; idx += THREADS) {
            int c   = idx / (KW * FF);
            int rem = idx - c * (KW * FF);
            int w   = rem / FF;
            int f   = rem - w * FF;
            sf[c][w][f] = filt[((size_t)f * C_TOT + c0 + c) * KW + w];
        }

        __syncthreads();

        // ---- compute: per channel, 12 x in regs, per-w 8 broadcast filt ----
        #pragma unroll 1
        for (int c = 0; c < CCHUNK; ++c) {
            float xr[12];
            const float4* xp = reinterpret_cast<const float4*>(&sx[c][tloc]);
            float4 x0 = xp[0], x1 = xp[1], x2 = xp[2];
            xr[0] = x0.x; xr[1] = x0.y; xr[2]  = x0.z; xr[3]  = x0.w;
            xr[4] = x1.x; xr[5] = x1.y; xr[6]  = x1.z; xr[7]  = x1.w;
            xr[8] = x2.x; xr[9] = x2.y; xr[10] = x2.z; xr[11] = x2.w;

            #pragma unroll
            for (int w = 0; w < KW; ++w) {
                float fr[8];
                const float4* fp = reinterpret_cast<const float4*>(&sf[c][w][fbase]);
                float4 f0 = fp[0], f1 = fp[1];
                fr[0] = f0.x; fr[1] = f0.y; fr[2] = f0.z; fr[3] = f0.w;
                fr[4] = f1.x; fr[5] = f1.y; fr[6] = f1.z; fr[7] = f1.w;

                #pragma unroll
                for (int ff = 0; ff < 8; ++ff)
                    #pragma unroll
                    for (int tt = 0; tt < 4; ++tt)
                        acc[ff][tt] = fmaf(fr[ff], xr[tt + w], acc[ff][tt]);
            }
        }
    }

    // ---- epilogue: add C*bias, store (float4 when fully in-bounds) ----
    const int tglobal = t0 + tloc;
    #pragma unroll
    for (int ff = 0; ff < 8; ++ff) {
        const int f = fbase + ff;
        const float b = (float)C_TOT * bias[f];
        float4 v;
        v.x = acc[ff][0] + b;
        v.y = acc[ff][1] + b;
        v.z = acc[ff][2] + b;
        v.w = acc[ff][3] + b;
        float* orow = out + ((size_t)n * FF + f) * OUT_W;
        if (tglobal + 3 < OUT_W) {
            *reinterpret_cast<float4*>(orow + tglobal) = v;
        } else {
            if (tglobal + 0 < OUT_W) orow[tglobal + 0] = v.x;
            if (tglobal + 1 < OUT_W) orow[tglobal + 1] = v.y;
            if (tglobal + 2 < OUT_W) orow[tglobal + 2] = v.z;
            if (tglobal + 3 < OUT_W) orow[tglobal + 3] = v.w;
        }
    }
}

extern "C" void kernel_launch(void* const* d_in, const int* in_sizes, int n_in,
                              void* d_out, int out_size)
{
    const float* x    = (const float*)d_in[0];   // [64, 64, 4096]
    const float* filt = (const float*)d_in[1];   // [64, 64, 9]
    const float* bias = (const float*)d_in[2];   // [64]
    float* out        = (float*)d_out;           // [64, 64, 4088]

    dim3 grid(N_TILES, NN);   // (32, 64)
    dim3 block(THREADS);
    conv1d_direct_kernel<<<grid, block>>>(x, filt, bias, out);
}

// round 6
// speedup vs baseline: 2.8418x; 2.8418x over previous
#include <cuda_runtime.h>
#include <cstdint>

// ---------------- problem constants ----------------
#define NN      64
#define C_TOT   64
#define W_IN    4096
#define FF      64
#define KW      9
#define OUT_W   (W_IN - KW + 1)      // 4088

#define TW      128                  // t-tile (M)
#define N_TILES 32
#define WORKS   (NN * N_TILES)       // 2048
#define GRID    148                  // persistent, 1 CTA/SM
#define THREADS 256                  // 8 warps; warp w handles M rows [16w,16w+16)

#define K_TOT   (C_TOT * KW)         // 576
#define KSTEPS  (K_TOT / 8)          // 72 k-steps of 8

// ---- SMEM layout (in 4-byte words) ----
// B: [k][f] stride 72 words (72 % 32 == 8 -> conflict-free fragment loads)
#define B_STR     72
#define B_WORDS   (K_TOT * B_STR)            // 41472
// x tile: [c][pos] stride 136 words (128 + 8 halo)
#define SX_STR    136
#define SX_WORDS  (C_TOT * SX_STR)           // 8704
// out tile (aliases x tile region): [f][t] stride 132 (conflict-free transpose)
#define SOUT_STR  132
#define SBIAS_W   (B_WORDS + SX_WORDS)       // 50176
#define SMEM_WORDS (SBIAS_W + 64)            // 50240
#define SMEM_BYTES (SMEM_WORDS * 4)          // 200960

__device__ __forceinline__ float tf32r(float v) {
    uint32_t u;
    asm("cvt.rna.tf32.f32 %0, %1;" : "=r"(u) : "f"(v));
    return __uint_as_float(u);
}

__device__ __forceinline__ void mma_tf32(float* d, uint32_t a0, uint32_t a1,
                                         uint32_t a2, uint32_t a3,
                                         uint32_t b0, uint32_t b1) {
    asm volatile(
        "mma.sync.aligned.m16n8k8.row.col.f32.tf32.tf32.f32 "
        "{%0,%1,%2,%3}, {%4,%5,%6,%7}, {%8,%9}, {%0,%1,%2,%3};"
        : "+f"(d[0]), "+f"(d[1]), "+f"(d[2]), "+f"(d[3])
        : "r"(a0), "r"(a1), "r"(a2), "r"(a3), "r"(b0), "r"(b1));
}

__global__ __launch_bounds__(THREADS, 1)
void conv1d_tf32_mmasync(const float* __restrict__ x,
                         const float* __restrict__ filt,
                         const float* __restrict__ bias,
                         float* __restrict__ out)
{
    extern __shared__ float sm[];
    float* sB    = sm;                 // [576][72]
    float* sX    = sm + B_WORDS;       // [64][136]
    float* sOut  = sX;                 // alias (used after K-loop)
    float* sBias = sm + SBIAS_W;       // [64]

    const int tid  = threadIdx.x;
    const int lane = tid & 31;
    const int warp = tid >> 5;         // 0..7
    const int g    = lane >> 2;        // groupID      0..7
    const int tg   = lane & 3;         // tid-in-group 0..3

    // ---- stage ALL filters once: sB[k*72 + f] = tf32(filt[f][k]) ----
    for (int i = tid; i < FF * (K_TOT / 4); i += THREADS) {
        int f  = i / (K_TOT / 4);
        int k4 = i - f * (K_TOT / 4);
        float4 v = *(const float4*)(filt + (size_t)f * K_TOT + k4 * 4);
        int k = k4 * 4;
        sB[(k + 0) * B_STR + f] = tf32r(v.x);
        sB[(k + 1) * B_STR + f] = tf32r(v.y);
        sB[(k + 2) * B_STR + f] = tf32r(v.z);
        sB[(k + 3) * B_STR + f] = tf32r(v.w);
    }
    if (tid < FF) sBias[tid] = (float)C_TOT * bias[tid];
    __syncthreads();

    for (int work = blockIdx.x; work < WORKS; work += GRID) {
        const int n  = work >> 5;
        const int t0 = (work & 31) * TW;

        // ---- stage x tile: sX[c][0..135] = tf32(x[n][c][t0 + pos]), 0 past end ----
        for (int i = tid; i < C_TOT * (SX_STR / 4); i += THREADS) {
            int c = i / (SX_STR / 4);
            int q = i - c * (SX_STR / 4);
            int gp = t0 + q * 4;
            const float* src = x + ((size_t)n * C_TOT + c) * W_IN + gp;
            float4 t;
            if (gp + 3 < W_IN) {
                float4 v = *(const float4*)src;
                t.x = tf32r(v.x); t.y = tf32r(v.y); t.z = tf32r(v.z); t.w = tf32r(v.w);
            } else {
                t.x = (gp + 0 < W_IN) ? tf32r(src[0]) : 0.0f;
                t.y = (gp + 1 < W_IN) ? tf32r(src[1]) : 0.0f;
                t.z = (gp + 2 < W_IN) ? tf32r(src[2]) : 0.0f;
                t.w = (gp + 3 < W_IN) ? tf32r(src[3]) : 0.0f;
            }
            *(float4*)(sX + c * SX_STR + q * 4) = t;
        }
        __syncthreads();

        // ---- K loop: 72 steps of k=8, per warp M=16 (rows warp*16 + g, +8) ----
        float acc[8][4];
        #pragma unroll
        for (int nb = 0; nb < 8; ++nb)
            #pragma unroll
            for (int j = 0; j < 4; ++j) acc[nb][j] = 0.0f;

        const int m0 = warp * 16 + g;
        // A trackers: col tg -> k=tg (c=0,w=tg); col tg+4 -> k=tg+4 (c=0,w=tg+4)
        int w0 = tg, w1 = tg + 4;
        int c1adj = (w1 >= KW) ? 1 : 0;            // tg+4 can reach 7 max; stays < 9
        const float* pa0 = sX + m0 + w0;
        const float* pa1 = sX + c1adj * SX_STR + m0 + (w1 - c1adj * KW);
        if (c1adj) w1 -= KW;
        // B base: row k0+tg, col nb*8+g
        const float* pb = sB + tg * B_STR + g;

        #pragma unroll 2
        for (int ks = 0; ks < KSTEPS; ++ks) {
            uint32_t a0 = __float_as_uint(pa0[0]);
            uint32_t a1 = __float_as_uint(pa0[8]);
            uint32_t a2 = __float_as_uint(pa1[0]);
            uint32_t a3 = __float_as_uint(pa1[8]);
            const float* pbk = pb;
            #pragma unroll
            for (int nb = 0; nb < 8; ++nb) {
                uint32_t b0 = __float_as_uint(pbk[0]);
                uint32_t b1 = __float_as_uint(pbk[4 * B_STR]);
                mma_tf32(acc[nb], a0, a1, a2, a3, b0, b1);
                pbk += 8;
            }
            pb += 8 * B_STR;
            // advance A by k+=8  (w' = w-1 unless w==0 -> 8, c+1)
            pa0 += (w0 >= 1) ? (SX_STR - 1) : 8;
            w0   = (w0 >= 1) ? (w0 - 1) : 8;
            pa1 += (w1 >= 1) ? (SX_STR - 1) : 8;
            w1   = (w1 >= 1) ? (w1 - 1) : 8;
        }
        __syncthreads();   // done reading sX; safe to alias as sOut

        // ---- epilogue: fragments -> sOut[f][t] (+ C*bias), conflict-free ----
        #pragma unroll
        for (int nb = 0; nb < 8; ++nb) {
            const int f0 = nb * 8 + 2 * tg;
            const int tl = warp * 16 + g;
            const float b0v = sBias[f0], b1v = sBias[f0 + 1];
            sOut[(size_t)f0 * SOUT_STR + tl]           = acc[nb][0] + b0v;
            sOut[(size_t)(f0 + 1) * SOUT_STR + tl]     = acc[nb][1] + b1v;
            sOut[(size_t)f0 * SOUT_STR + tl + 8]       = acc[nb][2] + b0v;
            sOut[(size_t)(f0 + 1) * SOUT_STR + tl + 8] = acc[nb][3] + b1v;
        }
        __syncthreads();

        // ---- coalesced float4 stores ----
        for (int i = tid; i < FF * (TW / 4); i += THREADS) {
            int f  = i >> 5;
            int q  = i & 31;
            int tp = t0 + q * 4;
            if (tp + 3 < OUT_W) {
                float4 v = *(const float4*)(sOut + (size_t)f * SOUT_STR + q * 4);
                *(float4*)(out + ((size_t)n * FF + f) * OUT_W + tp) = v;
            }
        }
        __syncthreads();   // sOut (=sX) reused by next tile's staging
    }
}

extern "C" void kernel_launch(void* const* d_in, const int* in_sizes, int n_in,
                              void* d_out, int out_size)
{
    const float* x    = (const float*)d_in[0];   // [64, 64, 4096]
    const float* filt = (const float*)d_in[1];   // [64, 64, 9]
    const float* bias = (const float*)d_in[2];   // [64]
    float* out        = (float*)d_out;           // [64, 64, 4088]

    cudaFuncSetAttribute(conv1d_tf32_mmasync,
                         cudaFuncAttributeMaxDynamicSharedMemorySize, SMEM_BYTES);
    conv1d_tf32_mmasync<<<GRID, THREADS, SMEM_BYTES>>>(x, filt, bias, out);
}

// round 11
// speedup vs baseline: 2.8976x; 1.0196x over previous
#include <cuda_runtime.h>
#include <cstdint>

// ---------------- problem constants ----------------
#define NN      64
#define C_TOT   64
#define W_IN    4096
#define FF      64
#define KW      9
#define OUT_W   (W_IN - KW + 1)      // 4088

#define TW      256                  // t-tile (M) per CTA
#define N_TILES 16                   // ceil(4088/256)
#define WORKS   (NN * N_TILES)       // 1024
#define GRID    148                  // persistent, 1 CTA/SM
#define THREADS 256                  // 8 warps, each M=32 x N=64

#define K_TOT    (C_TOT * KW)        // 576
#define C_CHUNK  32                  // channels staged per pass
#define KSTEPS_C 36                  // (32*9)/8 k-steps per chunk

// ---- SMEM layout (4-byte words) ----
// B stride 72: (8*tg+g)%32 all distinct for tg<4,g<8 -> conflict-free (s=72≡8 mod 32)
#define B_STR     72
#define B_WORDS   (K_TOT * B_STR)            // 41472
#define SX_STR    264                        // 256 + 8 halo
#define SX_ROWS   C_CHUNK
#define SX_WORDS  (SX_ROWS * SX_STR)         // 8448
#define SOUT_STR  260                        // transpose stride; banks 8tg+g distinct
#define SBIAS_W   (B_WORDS + SX_WORDS)       // 49920
#define SMEM_WORDS (SBIAS_W + 64)            // 49984
#define SMEM_BYTES (SMEM_WORDS * 4)          // 199936

__device__ __forceinline__ float tf32r(float v) {
    uint32_t u;
    asm("cvt.rna.tf32.f32 %0, %1;" : "=r"(u) : "f"(v));
    return __uint_as_float(u);
}

__device__ __forceinline__ void mma_tf32(float* d, uint32_t a0, uint32_t a1,
                                         uint32_t a2, uint32_t a3,
                                         uint32_t b0, uint32_t b1) {
    asm volatile(
        "mma.sync.aligned.m16n8k8.row.col.f32.tf32.tf32.f32 "
        "{%0,%1,%2,%3}, {%4,%5,%6,%7}, {%8,%9}, {%0,%1,%2,%3};"
        : "+f"(d[0]), "+f"(d[1]), "+f"(d[2]), "+f"(d[3])
        : "r"(a0), "r"(a1), "r"(a2), "r"(a3), "r"(b0), "r"(b1));
}

__global__ __launch_bounds__(THREADS, 1)
void conv1d_tf32_mmasync3(const float* __restrict__ x,
                          const float* __restrict__ filt,
                          const float* __restrict__ bias,
                          float* __restrict__ out)
{
    extern __shared__ float sm[];
    float* sB    = sm;                 // [576][72]
    float* sX    = sm + B_WORDS;       // [32][264]  (per-chunk)
    float* sOut  = sX;                 // alias after K-loop: [32][260] per half
    float* sBias = sm + SBIAS_W;       // [64]

    const int tid  = threadIdx.x;
    const int lane = tid & 31;
    const int warp = tid >> 5;         // 0..7
    const int g    = lane >> 2;        // 0..7
    const int tg   = lane & 3;         // 0..3
    const int m0   = warp * 32;        // warp's M rows [m0, m0+32)

    // ---- stage ALL filters once: sB[k*72 + f] = tf32(filt[f][k]) ----
    for (int i = tid; i < FF * (K_TOT / 4); i += THREADS) {
        int f  = i / (K_TOT / 4);
        int k4 = i - f * (K_TOT / 4);
        float4 v = *(const float4*)(filt + (size_t)f * K_TOT + k4 * 4);
        int k = k4 * 4;
        sB[(k + 0) * B_STR + f] = tf32r(v.x);
        sB[(k + 1) * B_STR + f] = tf32r(v.y);
        sB[(k + 2) * B_STR + f] = tf32r(v.z);
        sB[(k + 3) * B_STR + f] = tf32r(v.w);
    }
    if (tid < FF) sBias[tid] = (float)C_TOT * bias[tid];
    __syncthreads();

    for (int work = blockIdx.x; work < WORKS; work += GRID) {
        const int n  = work >> 4;            // work / 16
        const int t0 = (work & 15) * TW;

        float acc[2][8][4];
        #pragma unroll
        for (int mi = 0; mi < 2; ++mi)
            #pragma unroll
            for (int ni = 0; ni < 8; ++ni)
                #pragma unroll
                for (int j = 0; j < 4; ++j) acc[mi][ni][j] = 0.0f;

        // ==== two 32-channel passes: stage chunk -> 36 k-steps ====
        #pragma unroll 1
        for (int chunk = 0; chunk < 2; ++chunk) {
            __syncthreads();   // previous readers of sX done

            // ---- stage x chunk: sX[cl][0..263] = tf32(x[n][chunk*32+cl][t0+pos]) ----
            for (int i = tid; i < SX_ROWS * (SX_STR / 4); i += THREADS) {
                int cl = i / (SX_STR / 4);
                int q  = i - cl * (SX_STR / 4);
                int gp = t0 + q * 4;
                const float* src = x + ((size_t)n * C_TOT + chunk * C_CHUNK + cl) * W_IN + gp;
                float4 t;
                if (gp + 3 < W_IN) {
                    float4 v = *(const float4*)src;
                    t.x = tf32r(v.x); t.y = tf32r(v.y); t.z = tf32r(v.z); t.w = tf32r(v.w);
                } else {
                    t.x = (gp + 0 < W_IN) ? tf32r(src[0]) : 0.0f;
                    t.y = (gp + 1 < W_IN) ? tf32r(src[1]) : 0.0f;
                    t.z = (gp + 2 < W_IN) ? tf32r(src[2]) : 0.0f;
                    t.w = (gp + 3 < W_IN) ? tf32r(src[3]) : 0.0f;
                }
                *(float4*)(sX + cl * SX_STR + q * 4) = t;
            }
            __syncthreads();

            // ---- 36 k-steps, warp tile M=32 x N=64, ping-pong prefetch ----
            int w0 = tg, w1 = tg + 4;                    // local k trackers
            const float* pa0 = sX + m0 + g + w0;
            const float* pa1 = sX + m0 + g + w1;
            const float* pb  = sB + (chunk * (C_CHUNK * KW) + tg) * B_STR + g;

            uint32_t a[2][2][4];
            uint32_t b[2][8][2];

            #define LOAD_FRAGS(buf) do {                                        \
                a[buf][0][0] = __float_as_uint(pa0[0]);                         \
                a[buf][0][1] = __float_as_uint(pa0[8]);                         \
                a[buf][0][2] = __float_as_uint(pa1[0]);                         \
                a[buf][0][3] = __float_as_uint(pa1[8]);                         \
                a[buf][1][0] = __float_as_uint(pa0[16]);                        \
                a[buf][1][1] = __float_as_uint(pa0[24]);                        \
                a[buf][1][2] = __float_as_uint(pa1[16]);                        \
                a[buf][1][3] = __float_as_uint(pa1[24]);                        \
                _Pragma("unroll")                                               \
                for (int ni = 0; ni < 8; ++ni) {                                \
                    b[buf][ni][0] = __float_as_uint(pb[8 * ni]);                \
                    b[buf][ni][1] = __float_as_uint(pb[4 * B_STR + 8 * ni]);    \
                }                                                               \
            } while (0)

            #define ADV() do {                                                  \
                pa0 += (w0 >= 1) ? (SX_STR - 1) : 8;  w0 = (w0 >= 1) ? (w0 - 1) : 8; \
                pa1 += (w1 >= 1) ? (SX_STR - 1) : 8;  w1 = (w1 >= 1) ? (w1 - 1) : 8; \
                pb  += 8 * B_STR;                                               \
            } while (0)

            #define DO_MMA(buf) do {                                            \
                _Pragma("unroll")                                               \
                for (int mi = 0; mi < 2; ++mi)                                  \
                    _Pragma("unroll")                                           \
                    for (int ni = 0; ni < 8; ++ni)                              \
                        mma_tf32(acc[mi][ni],                                   \
                                 a[buf][mi][0], a[buf][mi][1],                  \
                                 a[buf][mi][2], a[buf][mi][3],                  \
                                 b[buf][ni][0], b[buf][ni][1]);                 \
            } while (0)

            LOAD_FRAGS(0);
            ADV();
            #pragma unroll 2
            for (int ks = 0; ks < KSTEPS_C; ++ks) {
                const int cur = ks & 1;
                if (ks + 1 < KSTEPS_C) {
                    LOAD_FRAGS(cur ^ 1);
                    ADV();
                }
                DO_MMA(cur);
            }
        }
        __syncthreads();   // K-loop done reading sX; safe to alias as sOut

        // ---- epilogue in two 32-filter halves (sOut = 32 x 260 alias) ----
        #pragma unroll 1
        for (int half = 0; half < 2; ++half) {
            #pragma unroll
            for (int mi = 0; mi < 2; ++mi) {
                const int tl = m0 + mi * 16 + g;
                #pragma unroll
                for (int nq = 0; nq < 4; ++nq) {
                    const int ni = half * 4 + nq;
                    const int f0 = ni * 8 + 2 * tg;       // global filter
                    const int fl = f0 - half * 32;        // local row 0..31
                    const float b0v = sBias[f0], b1v = sBias[f0 + 1];
                    sOut[(size_t)fl * SOUT_STR + tl]           = acc[mi][ni][0] + b0v;
                    sOut[(size_t)(fl + 1) * SOUT_STR + tl]     = acc[mi][ni][1] + b1v;
                    sOut[(size_t)fl * SOUT_STR + tl + 8]       = acc[mi][ni][2] + b0v;
                    sOut[(size_t)(fl + 1) * SOUT_STR + tl + 8] = acc[mi][ni][3] + b1v;
                }
            }
            __syncthreads();

            for (int i = tid; i < 32 * (TW / 4); i += THREADS) {
                int fl = i >> 6;            // / 64
                int q  = i & 63;
                int tp = t0 + q * 4;
                if (tp + 3 < OUT_W) {
                    float4 v = *(const float4*)(sOut + (size_t)fl * SOUT_STR + q * 4);
                    *(float4*)(out + ((size_t)n * FF + half * 32 + fl) * OUT_W + tp) = v;
                }
            }
            __syncthreads();
        }
    }
}

extern "C" void kernel_launch(void* const* d_in, const int* in_sizes, int n_in,
                              void* d_out, int out_size)
{
    const float* x    = (const float*)d_in[0];   // [64, 64, 4096]
    const float* filt = (const float*)d_in[1];   // [64, 64, 9]
    const float* bias = (const float*)d_in[2];   // [64]
    float* out        = (float*)d_out;           // [64, 64, 4088]

    cudaFuncSetAttribute(conv1d_tf32_mmasync3,
                         cudaFuncAttributeMaxDynamicSharedMemorySize, SMEM_BYTES);
    conv1d_tf32_mmasync3<<<GRID, THREADS, SMEM_BYTES>>>(x, filt, bias, out);
}